// round 11
// baseline (speedup 1.0000x reference)
#include <cuda_runtime.h>
#include <cuda_fp16.h>
#include <math.h>
#include <stdint.h>

#define NN 4096
#define DD 256
#define KTOP 10
#define MTOP 5
#define MU 2048
#define NCLS 31
#define NCHUNK 16
#define KSPLIT 512
#define BKT 64
#define NKC (KSPLIT / BKT)   // 8 k-chunks
#define LDT 72               // padded smem row stride (fp16 elems) = 144B
#define NSTG 3               // cp.async pipeline stages
#define GEMM_SMEM (NSTG * 128 * LDT * 2 * 2)   // 110592 B

// ---- scratch (device globals; no allocation allowed) ----
__device__ __align__(16) float g_sim[(size_t)NN * NN];   // g_sim[j*NN+i] = sim(src i, tgt j)
__device__ __align__(16) __half g_Asp[(size_t)NN * KSPLIT];  // tgt split [hi|lo]
__device__ __align__(16) __half g_Bsp[(size_t)NN * KSPLIT];  // src split [hi|hi]
__device__ float g_sqs[NN];
__device__ float g_sqt[NN];
__device__ int   g_assigned[NN];
__device__ float g_score[NN];
__device__ int   g_top_tgt[MU];
__device__ int   g_flab[MU];
__device__ int   g_rankp[8 * NN];
__device__ __align__(16) float g_spart[(size_t)NCHUNK * NN];
__device__ __align__(16) float g_smpart[(size_t)NCHUNK * NN];
__device__ float g_lsum[16];
__device__ float g_lcnt[16];

__device__ __forceinline__ bool better(float v, int i, float v2, int i2) {
    return (v > v2) || (v == v2 && i < i2);
}

static __device__ __forceinline__ uint32_t smem_u32(const void* p) {
    uint32_t a;
    asm("{ .reg .u64 t; cvta.to.shared.u64 t, %1; cvt.u32.u64 %0, t; }" : "=r"(a) : "l"(p));
    return a;
}

// e^x for x in [0,1]: degree-7 Taylor at 0.5; abs err < 2e-7 (pure FMA, no MUFU)
static __device__ __forceinline__ float exp01(float x) {
    float t = x - 0.5f;
    float p = 1.9841270e-4f;
    p = fmaf(p, t, 1.3888889e-3f);
    p = fmaf(p, t, 8.3333333e-3f);
    p = fmaf(p, t, 4.1666667e-2f);
    p = fmaf(p, t, 1.6666667e-1f);
    p = fmaf(p, t, 0.5f);
    p = fmaf(p, t, 1.0f);
    p = fmaf(p, t, 1.0f);
    return 1.64872127070013f * p;
}

// ---------------- K1: squared norms (both matrices) ----------------
__global__ __launch_bounds__(256) void norms_kernel(const float* __restrict__ src,
                                                    const float* __restrict__ tgt) {
    int row = blockIdx.x * 8 + (threadIdx.x >> 5);
    int lane = threadIdx.x & 31;
    const float* base = (row < NN) ? (src + (size_t)row * DD) : (tgt + (size_t)(row - NN) * DD);
    const float4* p = (const float4*)base;
    float4 a = p[lane];
    float4 b = p[lane + 32];
    float s = a.x*a.x + a.y*a.y + a.z*a.z + a.w*a.w
            + b.x*b.x + b.y*b.y + b.z*b.z + b.w*b.w;
    #pragma unroll
    for (int o = 16; o; o >>= 1) s += __shfl_xor_sync(0xffffffffu, s, o);
    if (lane == 0) {
        if (row < NN) g_sqs[row] = s; else g_sqt[row - NN] = s;
    }
}

// ---------------- K2: fp16 split conversion (src -> [hi|hi], tgt -> [hi|lo]) ----------------
__global__ __launch_bounds__(256) void convert_kernel(const float* __restrict__ src,
                                                      const float* __restrict__ tgt) {
    int t = threadIdx.x;
    int r = blockIdx.x * 4 + (t >> 6);
    int c = (t & 63) * 4;

    float4 x = *(const float4*)(src + (size_t)r * DD + c);
    __half2 h0 = make_half2(__float2half(x.x), __float2half(x.y));
    __half2 h1 = make_half2(__float2half(x.z), __float2half(x.w));
    uint2 hv = make_uint2(*(uint32_t*)&h0, *(uint32_t*)&h1);
    size_t rb = (size_t)r * KSPLIT;
    *(uint2*)&g_Bsp[rb + c]       = hv;
    *(uint2*)&g_Bsp[rb + 256 + c] = hv;

    float4 y = *(const float4*)(tgt + (size_t)r * DD + c);
    __half hx = __float2half(y.x), hy = __float2half(y.y);
    __half hz = __float2half(y.z), hw = __float2half(y.w);
    __half lx = __float2half(y.x - __half2float(hx));
    __half ly = __float2half(y.y - __half2float(hy));
    __half lz = __float2half(y.z - __half2float(hz));
    __half lw = __float2half(y.w - __half2float(hw));
    __half2 th0 = make_half2(hx, hy), th1 = make_half2(hz, hw);
    __half2 tl0 = make_half2(lx, ly), tl1 = make_half2(lz, lw);
    *(uint2*)&g_Asp[rb + c]       = make_uint2(*(uint32_t*)&th0, *(uint32_t*)&th1);
    *(uint2*)&g_Asp[rb + 256 + c] = make_uint2(*(uint32_t*)&tl0, *(uint32_t*)&tl1);
}

// ---------------- K3: fp16 mma.sync GEMM 128x128, warp 64x32, BKT=64, 3-stage ----------------
__global__ __launch_bounds__(256, 2) void gemm_mma_kernel() {
    extern __shared__ __half dsm[];
    __shared__ float s_sqs[128];
    __shared__ float s_sqt[128];

    int tid = threadIdx.x;
    int wid = tid >> 5, lane = tid & 31;
    int i0 = blockIdx.x * 128, j0 = blockIdx.y * 128;
    int mbase = (wid & 1) * 64;
    int nbase = (wid >> 1) * 32;

    if (tid < 128) { s_sqs[tid] = g_sqs[i0 + tid]; s_sqt[tid] = g_sqt[j0 + tid]; }

    const char* Ag = (const char*)(g_Asp + (size_t)j0 * KSPLIT);
    const char* Bg = (const char*)(g_Bsp + (size_t)i0 * KSPLIT);

    uint32_t aBase0 = smem_u32(&dsm[0]);
    uint32_t bBase0 = aBase0 + NSTG * 128 * LDT * 2;

    int rr = tid >> 3, cc8 = tid & 7;

    #define ISSUE_TILE(buf, kc) do {                                                     \
        uint32_t ab = aBase0 + (buf) * (128 * LDT * 2);                                  \
        uint32_t bb = bBase0 + (buf) * (128 * LDT * 2);                                  \
        _Pragma("unroll")                                                                \
        for (int u = 0; u < 4; u++) {                                                    \
            int row = rr + u * 32;                                                       \
            const char* ga = Ag + (size_t)row * (KSPLIT * 2) + (kc) * (BKT * 2) + cc8 * 16; \
            const char* gb = Bg + (size_t)row * (KSPLIT * 2) + (kc) * (BKT * 2) + cc8 * 16; \
            uint32_t sa = ab + (row * LDT + cc8 * 8) * 2;                                \
            uint32_t sb = bb + (row * LDT + cc8 * 8) * 2;                                \
            asm volatile("cp.async.cg.shared.global [%0], [%1], 16;" :: "r"(sa), "l"(ga)); \
            asm volatile("cp.async.cg.shared.global [%0], [%1], 16;" :: "r"(sb), "l"(gb)); \
        }                                                                                \
        asm volatile("cp.async.commit_group;");                                          \
    } while (0)

    float acc[4][4][4];
    #pragma unroll
    for (int mt = 0; mt < 4; mt++)
        #pragma unroll
        for (int nt = 0; nt < 4; nt++)
            #pragma unroll
            for (int e = 0; e < 4; e++) acc[mt][nt][e] = 0.f;

    ISSUE_TILE(0, 0);
    ISSUE_TILE(1, 1);

    int la_row = lane & 15;
    int la_kg  = lane >> 4;
    int lb_g   = lane >> 3;
    int lb_r   = lane & 7;
    int lb_row = ((lb_g >> 1) & 1) * 8 + lb_r;
    int lb_kc  = (lb_g & 1) * 8;

    int cur = 0, nxt = 2;
    for (int kc = 0; kc < NKC; kc++) {
        asm volatile("cp.async.wait_group 1;");
        __syncthreads();
        if (kc + 2 < NKC) {
            ISSUE_TILE(nxt, kc + 2);
        }

        uint32_t aT = aBase0 + cur * (128 * LDT * 2);
        uint32_t bT = bBase0 + cur * (128 * LDT * 2);

        #pragma unroll
        for (int ks = 0; ks < 4; ks++) {
            uint32_t a[4][4], bb4[2][4];
            #pragma unroll
            for (int mt = 0; mt < 4; mt++) {
                uint32_t addr = aT + ((mbase + mt * 16 + la_row) * LDT + ks * 16 + la_kg * 8) * 2;
                asm volatile("ldmatrix.sync.aligned.m8n8.x4.shared.b16 {%0,%1,%2,%3}, [%4];"
                             : "=r"(a[mt][0]), "=r"(a[mt][1]), "=r"(a[mt][2]), "=r"(a[mt][3])
                             : "r"(addr));
            }
            #pragma unroll
            for (int nt2 = 0; nt2 < 2; nt2++) {
                uint32_t addr = bT + ((nbase + nt2 * 16 + lb_row) * LDT + ks * 16 + lb_kc) * 2;
                asm volatile("ldmatrix.sync.aligned.m8n8.x4.shared.b16 {%0,%1,%2,%3}, [%4];"
                             : "=r"(bb4[nt2][0]), "=r"(bb4[nt2][1]), "=r"(bb4[nt2][2]), "=r"(bb4[nt2][3])
                             : "r"(addr));
            }
            #pragma unroll
            for (int mt = 0; mt < 4; mt++)
                #pragma unroll
                for (int nt = 0; nt < 4; nt++) {
                    int n2 = nt >> 1, h = nt & 1;
                    asm volatile(
                        "mma.sync.aligned.m16n8k16.row.col.f32.f16.f16.f32 "
                        "{%0,%1,%2,%3}, {%4,%5,%6,%7}, {%8,%9}, {%0,%1,%2,%3};"
                        : "+f"(acc[mt][nt][0]), "+f"(acc[mt][nt][1]),
                          "+f"(acc[mt][nt][2]), "+f"(acc[mt][nt][3])
                        : "r"(a[mt][0]), "r"(a[mt][1]), "r"(a[mt][2]), "r"(a[mt][3]),
                          "r"(bb4[n2][h * 2]), "r"(bb4[n2][h * 2 + 1]));
                }
        }
        cur = (cur == NSTG - 1) ? 0 : cur + 1;
        nxt = (nxt == NSTG - 1) ? 0 : nxt + 1;
    }

    int qr = lane >> 2, qc = lane & 3;
    #pragma unroll
    for (int mt = 0; mt < 4; mt++) {
        int jl1 = mbase + mt * 16 + qr;
        int jl2 = jl1 + 8;
        float sqj1 = s_sqt[jl1], sqj2 = s_sqt[jl2];
        #pragma unroll
        for (int nt = 0; nt < 4; nt++) {
            int il = nbase + nt * 8 + qc * 2;
            float si0 = s_sqs[il], si1 = s_sqs[il + 1];
            float d2a = fmaxf(sqj1 + si0 - 2.f * acc[mt][nt][0], 0.f);
            float d2b = fmaxf(sqj1 + si1 - 2.f * acc[mt][nt][1], 0.f);
            float d2c = fmaxf(sqj2 + si0 - 2.f * acc[mt][nt][2], 0.f);
            float d2d = fmaxf(sqj2 + si1 - 2.f * acc[mt][nt][3], 0.f);
            float2 o1 = make_float2(1.f / (sqrtf(d2a) + 1.f), 1.f / (sqrtf(d2b) + 1.f));
            float2 o2 = make_float2(1.f / (sqrtf(d2c) + 1.f), 1.f / (sqrtf(d2d) + 1.f));
            *(float2*)&g_sim[(size_t)(j0 + jl1) * NN + i0 + il] = o1;
            *(float2*)&g_sim[(size_t)(j0 + jl2) * NN + i0 + il] = o2;
        }
    }
}

// ---------------- K4: warp-per-column assigned label + score (smem labels) ----------------
__global__ __launch_bounds__(256) void target_kernel(const int* __restrict__ labels) {
    __shared__ int slab[NN];
    int tid = threadIdx.x;
    int lane = tid & 31;
    int j = blockIdx.x * 8 + (tid >> 5);
    const float* __restrict__ simrow = &g_sim[(size_t)j * NN];

    #pragma unroll
    for (int q = 0; q < NN / 256; q++) slab[tid + 256 * q] = __ldg(&labels[tid + 256 * q]);
    __syncthreads();

    float lv[KTOP]; int li[KTOP];
    #pragma unroll
    for (int t = 0; t < KTOP; t++) { lv[t] = -1.f; li[t] = NN + lane; }
    #pragma unroll 4
    for (int q = 0; q < NN / 32; q++) {
        int idx = q * 32 + lane;
        float v = __ldg(&simrow[idx]);
        if (better(v, idx, lv[KTOP - 1], li[KTOP - 1])) {
            float cv = v; int ci = idx;
            #pragma unroll
            for (int p = 0; p < KTOP; p++) {
                if (better(cv, ci, lv[p], li[p])) {
                    float tv = lv[p]; int ti = li[p];
                    lv[p] = cv; li[p] = ci; cv = tv; ci = ti;
                }
            }
        }
    }

    int labs[KTOP];
    #pragma unroll
    for (int it = 0; it < KTOP; it++) {
        float v = lv[0]; int idx = li[0];
        #pragma unroll
        for (int o = 16; o; o >>= 1) {
            float ov = __shfl_xor_sync(0xffffffffu, v, o);
            int   oi = __shfl_xor_sync(0xffffffffu, idx, o);
            if (better(ov, oi, v, idx)) { v = ov; idx = oi; }
        }
        labs[it] = slab[idx];
        if ((idx & 31) == lane && idx == li[0]) {
            #pragma unroll
            for (int p = 0; p < KTOP - 1; p++) { lv[p] = lv[p + 1]; li[p] = li[p + 1]; }
            lv[KTOP - 1] = -1.f; li[KTOP - 1] = NN + lane;
        }
    }

    int bestc = NCLS, bestn = 0;
    #pragma unroll
    for (int t = 0; t < KTOP; t++) {
        int c = labs[t], n = 0;
        #pragma unroll
        for (int u = 0; u < KTOP; u++) n += (labs[u] == c);
        if (n > bestn || (n == bestn && c < bestc)) { bestn = n; bestc = c; }
    }
    int assigned = bestc;
    if (lane == 0) g_assigned[j] = assigned;

    float sv[MTOP]; int si_[MTOP];
    float nv[MTOP]; int ni_[MTOP];
    #pragma unroll
    for (int t = 0; t < MTOP; t++) { sv[t] = 0.f; si_[t] = NN + lane; nv[t] = 0.f; ni_[t] = NN + lane; }
    #pragma unroll 4
    for (int q = 0; q < NN / 32; q++) {
        int idx = q * 32 + lane;
        float v = __ldg(&simrow[idx]);
        int lab = slab[idx];
        if (lab == assigned) {
            if (better(v, idx, sv[MTOP - 1], si_[MTOP - 1])) {
                float cv = v; int ci = idx;
                #pragma unroll
                for (int p = 0; p < MTOP; p++) {
                    if (better(cv, ci, sv[p], si_[p])) {
                        float tv = sv[p]; int ti = si_[p];
                        sv[p] = cv; si_[p] = ci; cv = tv; ci = ti;
                    }
                }
            }
        } else {
            if (better(v, idx, nv[MTOP - 1], ni_[MTOP - 1])) {
                float cv = v; int ci = idx;
                #pragma unroll
                for (int p = 0; p < MTOP; p++) {
                    if (better(cv, ci, nv[p], ni_[p])) {
                        float tv = nv[p]; int ti = ni_[p];
                        nv[p] = cv; ni_[p] = ci; cv = tv; ci = ti;
                    }
                }
            }
        }
    }

    float sumS = 0.f;
    #pragma unroll
    for (int it = 0; it < MTOP; it++) {
        float v = sv[0]; int idx = si_[0];
        #pragma unroll
        for (int o = 16; o; o >>= 1) {
            float ov = __shfl_xor_sync(0xffffffffu, v, o);
            int   oi = __shfl_xor_sync(0xffffffffu, idx, o);
            if (better(ov, oi, v, idx)) { v = ov; idx = oi; }
        }
        sumS += fmaxf(v, 0.f);
        if ((idx & 31) == lane && idx == si_[0]) {
            #pragma unroll
            for (int p = 0; p < MTOP - 1; p++) { sv[p] = sv[p + 1]; si_[p] = si_[p + 1]; }
            sv[MTOP - 1] = 0.f; si_[MTOP - 1] = NN + lane;
        }
    }
    float sumN = 0.f;
    #pragma unroll
    for (int it = 0; it < MTOP; it++) {
        float v = nv[0]; int idx = ni_[0];
        #pragma unroll
        for (int o = 16; o; o >>= 1) {
            float ov = __shfl_xor_sync(0xffffffffu, v, o);
            int   oi = __shfl_xor_sync(0xffffffffu, idx, o);
            if (better(ov, oi, v, idx)) { v = ov; idx = oi; }
        }
        sumN += fmaxf(v, 0.f);
        if ((idx & 31) == lane && idx == ni_[0]) {
            #pragma unroll
            for (int p = 0; p < MTOP - 1; p++) { nv[p] = nv[p + 1]; ni_[p] = ni_[p + 1]; }
            nv[MTOP - 1] = 0.f; ni_[MTOP - 1] = NN + lane;
        }
    }
    if (lane == 0) g_score[j] = sumS / sumN;
}

// ---------------- K5a: partial ranks (grid 16x8) ----------------
__global__ __launch_bounds__(256) void rank_partial_kernel() {
    __shared__ __align__(16) float chunk[512];
    int tid = threadIdx.x;
    int y = blockIdx.y;
    chunk[tid]       = g_score[y * 512 + tid];
    chunk[tid + 256] = g_score[y * 512 + tid + 256];
    __syncthreads();
    int i = blockIdx.x * 256 + tid;
    float v = __ldg(&g_score[i]);
    int kb0 = y * 512;
    int ra = 0, rb = 0, rc = 0, rd = 0;
    #pragma unroll 4
    for (int k4 = 0; k4 < 128; k4++) {
        float4 u = ((const float4*)chunk)[k4];
        int kb = kb0 + k4 * 4;
        ra += (u.x > v) || (u.x == v && (kb + 0) < i);
        rb += (u.y > v) || (u.y == v && (kb + 1) < i);
        rc += (u.z > v) || (u.z == v && (kb + 2) < i);
        rd += (u.w > v) || (u.w == v && (kb + 3) < i);
    }
    g_rankp[y * NN + i] = (ra + rb) + (rc + rd);
}

// ---------------- K5b: scatter top-MU ----------------
__global__ __launch_bounds__(256) void rank_scatter_kernel() {
    int i = blockIdx.x * 256 + threadIdx.x;
    int rank = 0;
    #pragma unroll
    for (int y = 0; y < 8; y++) rank += g_rankp[y * NN + i];
    if (rank < MU) {
        g_top_tgt[rank] = i;
        g_flab[rank] = g_assigned[i];
    }
}

// ---------------- K6: partial softmax sums (poly exp) ----------------
#define CCHUNK (MU / NCHUNK)   // 128
__global__ __launch_bounds__(256) void softmax_partial_kernel(const int* __restrict__ labels) {
    int i = blockIdx.x * 256 + threadIdx.x;
    int c0 = blockIdx.y * CCHUNK;
    __shared__ int srow[CCHUNK];
    __shared__ int sflab[CCHUNK];
    if (threadIdx.x < CCHUNK) {
        srow[threadIdx.x]  = g_top_tgt[c0 + threadIdx.x];
        sflab[threadIdx.x] = g_flab[c0 + threadIdx.x];
    }
    __syncthreads();
    int myLab = __ldg(&labels[i]);
    float s = 0.f, sm = 0.f;
    #pragma unroll 4
    for (int c = 0; c < CCHUNK; c++) {
        float v = g_sim[(size_t)srow[c] * NN + i];
        float e = exp01(v);
        s += e;
        if (sflab[c] == myLab) sm += e;
    }
    g_spart[(size_t)blockIdx.y * NN + i]  = s;
    g_smpart[(size_t)blockIdx.y * NN + i] = sm;
}

// ---------------- K7a: loss partials (16 blocks) ----------------
__global__ __launch_bounds__(256) void loss_partial_kernel(const int* __restrict__ labels) {
    int tid = threadIdx.x;
    __shared__ int cls[NCLS];
    if (tid < NCLS) cls[tid] = 0;
    __syncthreads();
    for (int c = tid; c < MU; c += 256) atomicAdd(&cls[g_flab[c]], 1);
    __syncthreads();

    int i = blockIdx.x * 256 + tid;
    float sum = 0.f, cntv = 0.f;
    int ns = cls[__ldg(&labels[i])];
    if (ns > 0 && ns < MU) {
        float s = 0.f, sm = 0.f;
        #pragma unroll
        for (int ch = 0; ch < NCHUNK; ch++) {
            s  += g_spart[(size_t)ch * NN + i];
            sm += g_smpart[(size_t)ch * NN + i];
        }
        sum = logf(s) - logf(sm);
        cntv = 1.f;
    }
    #pragma unroll
    for (int o = 16; o; o >>= 1) {
        sum  += __shfl_xor_sync(0xffffffffu, sum, o);
        cntv += __shfl_xor_sync(0xffffffffu, cntv, o);
    }
    __shared__ float ss[8], sc[8];
    if ((tid & 31) == 0) { ss[tid >> 5] = sum; sc[tid >> 5] = cntv; }
    __syncthreads();
    if (tid == 0) {
        float S = 0.f, C = 0.f;
        #pragma unroll
        for (int w = 0; w < 8; w++) { S += ss[w]; C += sc[w]; }
        g_lsum[blockIdx.x] = S;
        g_lcnt[blockIdx.x] = C;
    }
}

// ---------------- K7b: final loss ----------------
__global__ void loss_final_kernel(float* __restrict__ out) {
    if (threadIdx.x == 0) {
        float S = 0.f, C = 0.f;
        #pragma unroll
        for (int w = 0; w < 16; w++) { S += g_lsum[w]; C += g_lcnt[w]; }
        out[0] = S / C;
    }
}

// ---------------- launch ----------------
extern "C" void kernel_launch(void* const* d_in, const int* in_sizes, int n_in,
                              void* d_out, int out_size) {
    const float* src = (const float*)d_in[0];
    const int*   lab = (const int*)d_in[1];
    const float* tgt = (const float*)d_in[2];
    float* out = (float*)d_out;

    cudaFuncSetAttribute(gemm_mma_kernel,
                         cudaFuncAttributeMaxDynamicSharedMemorySize, GEMM_SMEM);

    norms_kernel<<<1024, 256>>>(src, tgt);       // launch 1
    convert_kernel<<<NN / 4, 256>>>(src, tgt);   // launch 2
    dim3 gg(NN / 128, NN / 128);
    gemm_mma_kernel<<<gg, 256, GEMM_SMEM>>>();   // launch 3
    target_kernel<<<NN / 8, 256>>>(lab);         // launch 4 (profiled slot)
    dim3 gr(16, 8);
    rank_partial_kernel<<<gr, 256>>>();
    rank_scatter_kernel<<<16, 256>>>();
    dim3 gs(NN / 256, NCHUNK);
    softmax_partial_kernel<<<gs, 256>>>(lab);
    loss_partial_kernel<<<16, 256>>>(lab);
    loss_final_kernel<<<1, 32>>>(out);
}

// round 13
// speedup vs baseline: 1.0003x; 1.0003x over previous
#include <cuda_runtime.h>
#include <cuda_fp16.h>
#include <math.h>
#include <stdint.h>

#define NN 4096
#define DD 256
#define KTOP 10
#define MTOP 5
#define MU 2048
#define NCLS 31
#define NCHUNK 16
#define KSPLIT 512
#define BKT 64
#define NKC (KSPLIT / BKT)   // 8 k-chunks
#define LDT 72               // padded smem row stride (fp16 elems) = 144B
#define NSTG 3               // cp.async pipeline stages
#define GEMM_SMEM (NSTG * 128 * LDT * 2 * 2)   // 110592 B

// ---- scratch (device globals; no allocation allowed) ----
__device__ __align__(16) float g_sim[(size_t)NN * NN];   // g_sim[j*NN+i] = sim(src i, tgt j)
__device__ __align__(16) __half g_Asp[(size_t)NN * KSPLIT];  // tgt split [hi|lo]
__device__ __align__(16) __half g_Bsp[(size_t)NN * KSPLIT];  // src split [hi|hi]
__device__ float g_sqs[NN];
__device__ float g_sqt[NN];
__device__ int   g_assigned[NN];
__device__ float g_score[NN];
__device__ int   g_top_tgt[MU];
__device__ int   g_flab[MU];
__device__ int   g_rankp[8 * NN];
__device__ __align__(16) float g_spart[(size_t)NCHUNK * NN];
__device__ __align__(16) float g_smpart[(size_t)NCHUNK * NN];
__device__ float g_lsum[16];
__device__ float g_lcnt[16];

__device__ __forceinline__ bool better(float v, int i, float v2, int i2) {
    return (v > v2) || (v == v2 && i < i2);
}

static __device__ __forceinline__ uint32_t smem_u32(const void* p) {
    uint32_t a;
    asm("{ .reg .u64 t; cvta.to.shared.u64 t, %1; cvt.u32.u64 %0, t; }" : "=r"(a) : "l"(p));
    return a;
}

// e^x for x in [0,1]: degree-7 Taylor at 0.5; abs err < 2e-7 (pure FMA, no MUFU)
static __device__ __forceinline__ float exp01(float x) {
    float t = x - 0.5f;
    float p = 1.9841270e-4f;
    p = fmaf(p, t, 1.3888889e-3f);
    p = fmaf(p, t, 8.3333333e-3f);
    p = fmaf(p, t, 4.1666667e-2f);
    p = fmaf(p, t, 1.6666667e-1f);
    p = fmaf(p, t, 0.5f);
    p = fmaf(p, t, 1.0f);
    p = fmaf(p, t, 1.0f);
    return 1.64872127070013f * p;
}

// ---------------- K1: squared norms (both matrices) ----------------
__global__ __launch_bounds__(256) void norms_kernel(const float* __restrict__ src,
                                                    const float* __restrict__ tgt) {
    int row = blockIdx.x * 8 + (threadIdx.x >> 5);
    int lane = threadIdx.x & 31;
    const float* base = (row < NN) ? (src + (size_t)row * DD) : (tgt + (size_t)(row - NN) * DD);
    const float4* p = (const float4*)base;
    float4 a = p[lane];
    float4 b = p[lane + 32];
    float s = a.x*a.x + a.y*a.y + a.z*a.z + a.w*a.w
            + b.x*b.x + b.y*b.y + b.z*b.z + b.w*b.w;
    #pragma unroll
    for (int o = 16; o; o >>= 1) s += __shfl_xor_sync(0xffffffffu, s, o);
    if (lane == 0) {
        if (row < NN) g_sqs[row] = s; else g_sqt[row - NN] = s;
    }
}

// ---------------- K2: fp16 split conversion ----------------
__global__ __launch_bounds__(256) void convert_kernel(const float* __restrict__ src,
                                                      const float* __restrict__ tgt) {
    int t = threadIdx.x;
    int r = blockIdx.x * 4 + (t >> 6);
    int c = (t & 63) * 4;

    float4 x = *(const float4*)(src + (size_t)r * DD + c);
    __half2 h0 = make_half2(__float2half(x.x), __float2half(x.y));
    __half2 h1 = make_half2(__float2half(x.z), __float2half(x.w));
    uint2 hv = make_uint2(*(uint32_t*)&h0, *(uint32_t*)&h1);
    size_t rb = (size_t)r * KSPLIT;
    *(uint2*)&g_Bsp[rb + c]       = hv;
    *(uint2*)&g_Bsp[rb + 256 + c] = hv;

    float4 y = *(const float4*)(tgt + (size_t)r * DD + c);
    __half hx = __float2half(y.x), hy = __float2half(y.y);
    __half hz = __float2half(y.z), hw = __float2half(y.w);
    __half lx = __float2half(y.x - __half2float(hx));
    __half ly = __float2half(y.y - __half2float(hy));
    __half lz = __float2half(y.z - __half2float(hz));
    __half lw = __float2half(y.w - __half2float(hw));
    __half2 th0 = make_half2(hx, hy), th1 = make_half2(hz, hw);
    __half2 tl0 = make_half2(lx, ly), tl1 = make_half2(lz, lw);
    *(uint2*)&g_Asp[rb + c]       = make_uint2(*(uint32_t*)&th0, *(uint32_t*)&th1);
    *(uint2*)&g_Asp[rb + 256 + c] = make_uint2(*(uint32_t*)&tl0, *(uint32_t*)&tl1);
}

// ---------------- K3: fp16 mma.sync GEMM 128x128, warp 64x32, BKT=64, 3-stage ----------------
__global__ __launch_bounds__(256, 2) void gemm_mma_kernel() {
    extern __shared__ __half dsm[];
    __shared__ float s_sqs[128];
    __shared__ float s_sqt[128];

    int tid = threadIdx.x;
    int wid = tid >> 5, lane = tid & 31;
    int i0 = blockIdx.x * 128, j0 = blockIdx.y * 128;
    int mbase = (wid & 1) * 64;
    int nbase = (wid >> 1) * 32;

    if (tid < 128) { s_sqs[tid] = g_sqs[i0 + tid]; s_sqt[tid] = g_sqt[j0 + tid]; }

    const char* Ag = (const char*)(g_Asp + (size_t)j0 * KSPLIT);
    const char* Bg = (const char*)(g_Bsp + (size_t)i0 * KSPLIT);

    uint32_t aBase0 = smem_u32(&dsm[0]);
    uint32_t bBase0 = aBase0 + NSTG * 128 * LDT * 2;

    int rr = tid >> 3, cc8 = tid & 7;

    #define ISSUE_TILE(buf, kc) do {                                                     \
        uint32_t ab = aBase0 + (buf) * (128 * LDT * 2);                                  \
        uint32_t bb = bBase0 + (buf) * (128 * LDT * 2);                                  \
        _Pragma("unroll")                                                                \
        for (int u = 0; u < 4; u++) {                                                    \
            int row = rr + u * 32;                                                       \
            const char* ga = Ag + (size_t)row * (KSPLIT * 2) + (kc) * (BKT * 2) + cc8 * 16; \
            const char* gb = Bg + (size_t)row * (KSPLIT * 2) + (kc) * (BKT * 2) + cc8 * 16; \
            uint32_t sa = ab + (row * LDT + cc8 * 8) * 2;                                \
            uint32_t sb = bb + (row * LDT + cc8 * 8) * 2;                                \
            asm volatile("cp.async.cg.shared.global [%0], [%1], 16;" :: "r"(sa), "l"(ga)); \
            asm volatile("cp.async.cg.shared.global [%0], [%1], 16;" :: "r"(sb), "l"(gb)); \
        }                                                                                \
        asm volatile("cp.async.commit_group;");                                          \
    } while (0)

    float acc[4][4][4];
    #pragma unroll
    for (int mt = 0; mt < 4; mt++)
        #pragma unroll
        for (int nt = 0; nt < 4; nt++)
            #pragma unroll
            for (int e = 0; e < 4; e++) acc[mt][nt][e] = 0.f;

    ISSUE_TILE(0, 0);
    ISSUE_TILE(1, 1);

    int la_row = lane & 15;
    int la_kg  = lane >> 4;
    int lb_g   = lane >> 3;
    int lb_r   = lane & 7;
    int lb_row = ((lb_g >> 1) & 1) * 8 + lb_r;
    int lb_kc  = (lb_g & 1) * 8;

    int cur = 0, nxt = 2;
    for (int kc = 0; kc < NKC; kc++) {
        asm volatile("cp.async.wait_group 1;");
        __syncthreads();
        if (kc + 2 < NKC) {
            ISSUE_TILE(nxt, kc + 2);
        }

        uint32_t aT = aBase0 + cur * (128 * LDT * 2);
        uint32_t bT = bBase0 + cur * (128 * LDT * 2);

        #pragma unroll
        for (int ks = 0; ks < 4; ks++) {
            uint32_t a[4][4], bb4[2][4];
            #pragma unroll
            for (int mt = 0; mt < 4; mt++) {
                uint32_t addr = aT + ((mbase + mt * 16 + la_row) * LDT + ks * 16 + la_kg * 8) * 2;
                asm volatile("ldmatrix.sync.aligned.m8n8.x4.shared.b16 {%0,%1,%2,%3}, [%4];"
                             : "=r"(a[mt][0]), "=r"(a[mt][1]), "=r"(a[mt][2]), "=r"(a[mt][3])
                             : "r"(addr));
            }
            #pragma unroll
            for (int nt2 = 0; nt2 < 2; nt2++) {
                uint32_t addr = bT + ((nbase + nt2 * 16 + lb_row) * LDT + ks * 16 + lb_kc) * 2;
                asm volatile("ldmatrix.sync.aligned.m8n8.x4.shared.b16 {%0,%1,%2,%3}, [%4];"
                             : "=r"(bb4[nt2][0]), "=r"(bb4[nt2][1]), "=r"(bb4[nt2][2]), "=r"(bb4[nt2][3])
                             : "r"(addr));
            }
            #pragma unroll
            for (int mt = 0; mt < 4; mt++)
                #pragma unroll
                for (int nt = 0; nt < 4; nt++) {
                    int n2 = nt >> 1, h = nt & 1;
                    asm volatile(
                        "mma.sync.aligned.m16n8k16.row.col.f32.f16.f16.f32 "
                        "{%0,%1,%2,%3}, {%4,%5,%6,%7}, {%8,%9}, {%0,%1,%2,%3};"
                        : "+f"(acc[mt][nt][0]), "+f"(acc[mt][nt][1]),
                          "+f"(acc[mt][nt][2]), "+f"(acc[mt][nt][3])
                        : "r"(a[mt][0]), "r"(a[mt][1]), "r"(a[mt][2]), "r"(a[mt][3]),
                          "r"(bb4[n2][h * 2]), "r"(bb4[n2][h * 2 + 1]));
                }
        }
        cur = (cur == NSTG - 1) ? 0 : cur + 1;
        nxt = (nxt == NSTG - 1) ? 0 : nxt + 1;
    }

    int qr = lane >> 2, qc = lane & 3;
    #pragma unroll
    for (int mt = 0; mt < 4; mt++) {
        int jl1 = mbase + mt * 16 + qr;
        int jl2 = jl1 + 8;
        float sqj1 = s_sqt[jl1], sqj2 = s_sqt[jl2];
        #pragma unroll
        for (int nt = 0; nt < 4; nt++) {
            int il = nbase + nt * 8 + qc * 2;
            float si0 = s_sqs[il], si1 = s_sqs[il + 1];
            float d2a = fmaxf(sqj1 + si0 - 2.f * acc[mt][nt][0], 0.f);
            float d2b = fmaxf(sqj1 + si1 - 2.f * acc[mt][nt][1], 0.f);
            float d2c = fmaxf(sqj2 + si0 - 2.f * acc[mt][nt][2], 0.f);
            float d2d = fmaxf(sqj2 + si1 - 2.f * acc[mt][nt][3], 0.f);
            float2 o1 = make_float2(1.f / (sqrtf(d2a) + 1.f), 1.f / (sqrtf(d2b) + 1.f));
            float2 o2 = make_float2(1.f / (sqrtf(d2c) + 1.f), 1.f / (sqrtf(d2d) + 1.f));
            *(float2*)&g_sim[(size_t)(j0 + jl1) * NN + i0 + il] = o1;
            *(float2*)&g_sim[(size_t)(j0 + jl2) * NN + i0 + il] = o2;
        }
    }
}

// guarded insert into sorted (value desc, idx asc) list of length L
#define INS(v_, i_, LV, LI, L) do {                                   \
    if (better((v_), (i_), LV[(L)-1], LI[(L)-1])) {                   \
        float cv = (v_); int ci = (i_);                               \
        _Pragma("unroll")                                             \
        for (int p_ = 0; p_ < (L); p_++) {                            \
            if (better(cv, ci, LV[p_], LI[p_])) {                     \
                float tv_ = LV[p_]; int ti_ = LI[p_];                 \
                LV[p_] = cv; LI[p_] = ci; cv = tv_; ci = ti_;         \
            }                                                         \
        }                                                             \
    }                                                                 \
} while (0)

// ---------------- K4: warp-per-column, quad-granular scans ----------------
__global__ __launch_bounds__(256) void target_kernel(const int* __restrict__ labels) {
    __shared__ uint32_t slab4[NN / 4];   // 4 packed label bytes per word
    int tid = threadIdx.x;
    int lane = tid & 31;
    int j = blockIdx.x * 8 + (tid >> 5);
    const float4* __restrict__ simrow4 = (const float4*)&g_sim[(size_t)j * NN];

    #pragma unroll
    for (int q = 0; q < NN / 4 / 256; q++) {
        int i4 = tid + 256 * q;
        int4 l = *(const int4*)(labels + i4 * 4);
        slab4[i4] = (uint32_t)(l.x & 0xFF) | ((uint32_t)(l.y & 0xFF) << 8)
                  | ((uint32_t)(l.z & 0xFF) << 16) | ((uint32_t)(l.w & 0xFF) << 24);
    }
    __syncthreads();

    // ---- pass 1: per-lane top-10, quad guarded ----
    float lv[KTOP]; int li[KTOP];
    #pragma unroll
    for (int t = 0; t < KTOP; t++) { lv[t] = -1.f; li[t] = NN + lane; }
    for (int q = 0; q < NN / 128; q++) {
        float4 v4 = __ldg(&simrow4[q * 32 + lane]);
        float mx = fmaxf(fmaxf(v4.x, v4.y), fmaxf(v4.z, v4.w));
        if (mx >= lv[KTOP - 1]) {
            int base = q * 128 + lane * 4;
            INS(v4.x, base + 0, lv, li, KTOP);
            INS(v4.y, base + 1, lv, li, KTOP);
            INS(v4.z, base + 2, lv, li, KTOP);
            INS(v4.w, base + 3, lv, li, KTOP);
        }
    }

    // ---- warp merge: 10 argmax rounds; removal keyed on unique idx ----
    int labs[KTOP];
    #pragma unroll
    for (int it = 0; it < KTOP; it++) {
        float v = lv[0]; int idx = li[0];
        #pragma unroll
        for (int o = 16; o; o >>= 1) {
            float ov = __shfl_xor_sync(0xffffffffu, v, o);
            int   oi = __shfl_xor_sync(0xffffffffu, idx, o);
            if (better(ov, oi, v, idx)) { v = ov; idx = oi; }
        }
        labs[it] = (int)((slab4[idx >> 2] >> ((idx & 3) * 8)) & 0xFF);
        if (idx == li[0]) {   // element indices unique across lanes
            #pragma unroll
            for (int p = 0; p < KTOP - 1; p++) { lv[p] = lv[p + 1]; li[p] = li[p + 1]; }
            lv[KTOP - 1] = -1.f; li[KTOP - 1] = NN + lane;
        }
    }

    int bestc = NCLS, bestn = 0;
    #pragma unroll
    for (int t = 0; t < KTOP; t++) {
        int c = labs[t], n = 0;
        #pragma unroll
        for (int u = 0; u < KTOP; u++) n += (labs[u] == c);
        if (n > bestn || (n == bestn && c < bestc)) { bestn = n; bestc = c; }
    }
    int assigned = bestc;
    if (lane == 0) g_assigned[j] = assigned;
    uint32_t assigned4 = (uint32_t)assigned * 0x01010101u;

    // ---- pass 2: per-lane top-5 same / not-same, quad guarded ----
    float sv[MTOP]; int si_[MTOP];
    float nv[MTOP]; int ni_[MTOP];
    #pragma unroll
    for (int t = 0; t < MTOP; t++) { sv[t] = 0.f; si_[t] = NN + lane; nv[t] = 0.f; ni_[t] = NN + lane; }
    for (int q = 0; q < NN / 128; q++) {
        float4 v4 = __ldg(&simrow4[q * 32 + lane]);
        uint32_t eq = __vcmpeq4(slab4[q * 32 + lane], assigned4);
        float mx = fmaxf(fmaxf(v4.x, v4.y), fmaxf(v4.z, v4.w));
        if (eq == 0u) {
            if (mx >= nv[MTOP - 1]) {
                int base = q * 128 + lane * 4;
                INS(v4.x, base + 0, nv, ni_, MTOP);
                INS(v4.y, base + 1, nv, ni_, MTOP);
                INS(v4.z, base + 2, nv, ni_, MTOP);
                INS(v4.w, base + 3, nv, ni_, MTOP);
            }
        } else {
            int base = q * 128 + lane * 4;
            float vv[4] = { v4.x, v4.y, v4.z, v4.w };
            #pragma unroll
            for (int e = 0; e < 4; e++) {
                if ((eq >> (e * 8)) & 0xFFu) {
                    INS(vv[e], base + e, sv, si_, MTOP);
                } else {
                    INS(vv[e], base + e, nv, ni_, MTOP);
                }
            }
        }
    }

    float sumS = 0.f;
    #pragma unroll
    for (int it = 0; it < MTOP; it++) {
        float v = sv[0]; int idx = si_[0];
        #pragma unroll
        for (int o = 16; o; o >>= 1) {
            float ov = __shfl_xor_sync(0xffffffffu, v, o);
            int   oi = __shfl_xor_sync(0xffffffffu, idx, o);
            if (better(ov, oi, v, idx)) { v = ov; idx = oi; }
        }
        sumS += fmaxf(v, 0.f);
        if (idx == si_[0]) {
            #pragma unroll
            for (int p = 0; p < MTOP - 1; p++) { sv[p] = sv[p + 1]; si_[p] = si_[p + 1]; }
            sv[MTOP - 1] = 0.f; si_[MTOP - 1] = NN + lane;
        }
    }
    float sumN = 0.f;
    #pragma unroll
    for (int it = 0; it < MTOP; it++) {
        float v = nv[0]; int idx = ni_[0];
        #pragma unroll
        for (int o = 16; o; o >>= 1) {
            float ov = __shfl_xor_sync(0xffffffffu, v, o);
            int   oi = __shfl_xor_sync(0xffffffffu, idx, o);
            if (better(ov, oi, v, idx)) { v = ov; idx = oi; }
        }
        sumN += fmaxf(v, 0.f);
        if (idx == ni_[0]) {
            #pragma unroll
            for (int p = 0; p < MTOP - 1; p++) { nv[p] = nv[p + 1]; ni_[p] = ni_[p + 1]; }
            nv[MTOP - 1] = 0.f; ni_[MTOP - 1] = NN + lane;
        }
    }
    if (lane == 0) g_score[j] = sumS / sumN;
}

// ---------------- K5a: partial ranks (grid 16x8) ----------------
__global__ __launch_bounds__(256) void rank_partial_kernel() {
    __shared__ __align__(16) float chunk[512];
    int tid = threadIdx.x;
    int y = blockIdx.y;
    chunk[tid]       = g_score[y * 512 + tid];
    chunk[tid + 256] = g_score[y * 512 + tid + 256];
    __syncthreads();
    int i = blockIdx.x * 256 + tid;
    float v = __ldg(&g_score[i]);
    int kb0 = y * 512;
    int ra = 0, rb = 0, rc = 0, rd = 0;
    #pragma unroll 4
    for (int k4 = 0; k4 < 128; k4++) {
        float4 u = ((const float4*)chunk)[k4];
        int kb = kb0 + k4 * 4;
        ra += (u.x > v) || (u.x == v && (kb + 0) < i);
        rb += (u.y > v) || (u.y == v && (kb + 1) < i);
        rc += (u.z > v) || (u.z == v && (kb + 2) < i);
        rd += (u.w > v) || (u.w == v && (kb + 3) < i);
    }
    g_rankp[y * NN + i] = (ra + rb) + (rc + rd);
}

// ---------------- K5b: scatter top-MU ----------------
__global__ __launch_bounds__(256) void rank_scatter_kernel() {
    int i = blockIdx.x * 256 + threadIdx.x;
    int rank = 0;
    #pragma unroll
    for (int y = 0; y < 8; y++) rank += g_rankp[y * NN + i];
    if (rank < MU) {
        g_top_tgt[rank] = i;
        g_flab[rank] = g_assigned[i];
    }
}

// ---------------- K6: partial softmax sums (poly exp) ----------------
#define CCHUNK (MU / NCHUNK)   // 128
__global__ __launch_bounds__(256) void softmax_partial_kernel(const int* __restrict__ labels) {
    int i = blockIdx.x * 256 + threadIdx.x;
    int c0 = blockIdx.y * CCHUNK;
    __shared__ int srow[CCHUNK];
    __shared__ int sflab[CCHUNK];
    if (threadIdx.x < CCHUNK) {
        srow[threadIdx.x]  = g_top_tgt[c0 + threadIdx.x];
        sflab[threadIdx.x] = g_flab[c0 + threadIdx.x];
    }
    __syncthreads();
    int myLab = __ldg(&labels[i]);
    float s = 0.f, sm = 0.f;
    #pragma unroll 4
    for (int c = 0; c < CCHUNK; c++) {
        float v = g_sim[(size_t)srow[c] * NN + i];
        float e = exp01(v);
        s += e;
        if (sflab[c] == myLab) sm += e;
    }
    g_spart[(size_t)blockIdx.y * NN + i]  = s;
    g_smpart[(size_t)blockIdx.y * NN + i] = sm;
}

// ---------------- K7a: loss partials (16 blocks) ----------------
__global__ __launch_bounds__(256) void loss_partial_kernel(const int* __restrict__ labels) {
    int tid = threadIdx.x;
    __shared__ int cls[NCLS];
    if (tid < NCLS) cls[tid] = 0;
    __syncthreads();
    for (int c = tid; c < MU; c += 256) atomicAdd(&cls[g_flab[c]], 1);
    __syncthreads();

    int i = blockIdx.x * 256 + tid;
    float sum = 0.f, cntv = 0.f;
    int ns = cls[__ldg(&labels[i])];
    if (ns > 0 && ns < MU) {
        float s = 0.f, sm = 0.f;
        #pragma unroll
        for (int ch = 0; ch < NCHUNK; ch++) {
            s  += g_spart[(size_t)ch * NN + i];
            sm += g_smpart[(size_t)ch * NN + i];
        }
        sum = logf(s) - logf(sm);
        cntv = 1.f;
    }
    #pragma unroll
    for (int o = 16; o; o >>= 1) {
        sum  += __shfl_xor_sync(0xffffffffu, sum, o);
        cntv += __shfl_xor_sync(0xffffffffu, cntv, o);
    }
    __shared__ float ss[8], sc[8];
    if ((tid & 31) == 0) { ss[tid >> 5] = sum; sc[tid >> 5] = cntv; }
    __syncthreads();
    if (tid == 0) {
        float S = 0.f, C = 0.f;
        #pragma unroll
        for (int w = 0; w < 8; w++) { S += ss[w]; C += sc[w]; }
        g_lsum[blockIdx.x] = S;
        g_lcnt[blockIdx.x] = C;
    }
}

// ---------------- K7b: final loss ----------------
__global__ void loss_final_kernel(float* __restrict__ out) {
    if (threadIdx.x == 0) {
        float S = 0.f, C = 0.f;
        #pragma unroll
        for (int w = 0; w < 16; w++) { S += g_lsum[w]; C += g_lcnt[w]; }
        out[0] = S / C;
    }
}

// ---------------- launch ----------------
extern "C" void kernel_launch(void* const* d_in, const int* in_sizes, int n_in,
                              void* d_out, int out_size) {
    const float* src = (const float*)d_in[0];
    const int*   lab = (const int*)d_in[1];
    const float* tgt = (const float*)d_in[2];
    float* out = (float*)d_out;

    cudaFuncSetAttribute(gemm_mma_kernel,
                         cudaFuncAttributeMaxDynamicSharedMemorySize, GEMM_SMEM);

    norms_kernel<<<1024, 256>>>(src, tgt);       // launch 1
    convert_kernel<<<NN / 4, 256>>>(src, tgt);   // launch 2
    dim3 gg(NN / 128, NN / 128);
    gemm_mma_kernel<<<gg, 256, GEMM_SMEM>>>();   // launch 3
    target_kernel<<<NN / 8, 256>>>(lab);         // launch 4 (profiled slot)
    dim3 gr(16, 8);
    rank_partial_kernel<<<gr, 256>>>();
    rank_scatter_kernel<<<16, 256>>>();
    dim3 gs(NN / 256, NCHUNK);
    softmax_partial_kernel<<<gs, 256>>>(lab);
    loss_partial_kernel<<<16, 256>>>(lab);
    loss_final_kernel<<<1, 32>>>(out);
}